// round 2
// baseline (speedup 1.0000x reference)
#include <cuda_runtime.h>
#include <cuda_bf16.h>

#define SHORT_CUT   4.0f
#define LONG_CUT    10.0f
#define KEHALF      7.199822675975274f
#define INV_SHORT   0.25f        // 1/SHORT_CUT
#define INV_LR2     0.01f        // 1/(LONG_CUT*LONG_CUT)
#define TWO_OVER_LC 0.2f         // 2/LONG_CUT

// ---------------------------------------------------------------------------
// Zero the output (it is poisoned to 0xAA by the harness).
// ---------------------------------------------------------------------------
__global__ void zero_out_kernel(float* __restrict__ out, int n)
{
    int i = blockIdx.x * blockDim.x + threadIdx.x;
    int n4 = n >> 2;
    float4* out4 = reinterpret_cast<float4*>(out);
    for (int k = i; k < n4; k += gridDim.x * blockDim.x)
        out4[k] = make_float4(0.f, 0.f, 0.f, 0.f);
    int tail_start = n4 << 2;
    for (int k = tail_start + i; k < n; k += gridDim.x * blockDim.x)
        out[k] = 0.f;
}

// ---------------------------------------------------------------------------
// Per-edge energy
// ---------------------------------------------------------------------------
__device__ __forceinline__ float edge_energy(float d, float qq)
{
    float s2    = fmaf(d, d, 1.0f);
    float r     = rsqrtf(s2);          // 1/d_sh
    float dsh   = s2 * r;              // d_sh
    float inv_d = __fdividef(1.0f, d); // 1/d

    float E_ord = fmaf(d,   INV_LR2, inv_d) - TWO_OVER_LC;
    float E_shd = fmaf(dsh, INV_LR2, r)     - TWO_OVER_LC;

    // smooth switch: 6x^5 - 15x^4 + 10x^3 for d < SHORT_CUT, else 1
    float x  = d * INV_SHORT;
    float x3 = x * x * x;
    float sw = fmaf(fmaf(6.0f, x, -15.0f), x, 10.0f) * x3;
    sw = (d < SHORT_CUT) ? sw : 1.0f;

    // csw*E_shd + sw*E_ord == E_shd + sw*(E_ord - E_shd)
    float mix = fmaf(sw, E_ord - E_shd, E_shd);
    return KEHALF * qq * mix;
}

// ---------------------------------------------------------------------------
// Main kernel: 8 edges per thread (two float4/int4 packets per stream).
// ---------------------------------------------------------------------------
#define EPT 8  // edges per thread (must be multiple of 4)

__global__ void __launch_bounds__(256)
edges_kernel(const float* __restrict__ charges,
             const float* __restrict__ distances,
             const int*   __restrict__ idx_i,
             const int*   __restrict__ idx_j,
             float*       __restrict__ out,
             int n_edges)
{
    long long t    = blockIdx.x * (long long)blockDim.x + threadIdx.x;
    long long base = t * EPT;

    if (base + EPT <= n_edges) {
        // ---- fully vectorized fast path ----
        float dv[EPT]; int iv[EPT], jv[EPT];

#pragma unroll
        for (int p = 0; p < EPT / 4; p++) {
            float4 d4 = reinterpret_cast<const float4*>(distances + base)[p];
            int4   i4 = reinterpret_cast<const int4*>(idx_i + base)[p];
            int4   j4 = reinterpret_cast<const int4*>(idx_j + base)[p];
            dv[p*4+0] = d4.x; dv[p*4+1] = d4.y; dv[p*4+2] = d4.z; dv[p*4+3] = d4.w;
            iv[p*4+0] = i4.x; iv[p*4+1] = i4.y; iv[p*4+2] = i4.z; iv[p*4+3] = i4.w;
            jv[p*4+0] = j4.x; jv[p*4+1] = j4.y; jv[p*4+2] = j4.z; jv[p*4+3] = j4.w;
        }

        // gather charges only for active edges (predicated LDG, still pipelined)
        float qq[EPT];
        bool  act[EPT];
#pragma unroll
        for (int k = 0; k < EPT; k++) {
            act[k] = (dv[k] <= LONG_CUT);
            float qi = 0.f, qj = 0.f;
            if (act[k]) {
                qi = __ldg(&charges[iv[k]]);
                qj = __ldg(&charges[jv[k]]);
            }
            qq[k] = qi * qj;
        }

#pragma unroll
        for (int k = 0; k < EPT; k++) {
            if (act[k]) {
                float e = edge_energy(dv[k], qq[k]);
                atomicAdd(&out[iv[k]], e);   // result unused -> RED
            }
        }
    } else if (base < n_edges) {
        // ---- scalar tail ----
        for (long long e_idx = base; e_idx < n_edges; e_idx++) {
            float d = distances[e_idx];
            if (d <= LONG_CUT) {
                float qi = __ldg(&charges[idx_i[e_idx]]);
                float qj = __ldg(&charges[idx_j[e_idx]]);
                atomicAdd(&out[idx_i[e_idx]], edge_energy(d, qi * qj));
            }
        }
    }
}

// ---------------------------------------------------------------------------
// Launch
// ---------------------------------------------------------------------------
extern "C" void kernel_launch(void* const* d_in, const int* in_sizes, int n_in,
                              void* d_out, int out_size)
{
    const float* charges   = (const float*)d_in[0];
    const float* distances = (const float*)d_in[1];
    const int*   idx_i     = (const int*)d_in[2];
    const int*   idx_j     = (const int*)d_in[3];
    float*       out       = (float*)d_out;

    int n_edges = in_sizes[1];

    // zero output (poisoned by harness)
    {
        int threads = 256;
        int blocks  = (out_size / 4 + threads - 1) / threads;
        if (blocks < 1) blocks = 1;
        if (blocks > 4096) blocks = 4096;
        zero_out_kernel<<<blocks, threads>>>(out, out_size);
    }

    // main edge kernel
    {
        long long n_thr = ((long long)n_edges + EPT - 1) / EPT;
        int threads = 256;
        long long blocks = (n_thr + threads - 1) / threads;
        edges_kernel<<<(unsigned)blocks, threads>>>(charges, distances,
                                                    idx_i, idx_j, out, n_edges);
    }
}

// round 4
// speedup vs baseline: 1.3784x; 1.3784x over previous
#include <cuda_runtime.h>
#include <cuda_bf16.h>

#define SHORT_CUT   4.0f
#define LONG_CUT    10.0f
#define KEHALF      7.199822675975274f
#define INV_SHORT   0.25f        // 1/SHORT_CUT
#define INV_LR2     0.01f        // 1/(LONG_CUT*LONG_CUT)
#define TWO_OVER_LC 0.2f         // 2/LONG_CUT

// ---------------------------------------------------------------------------
// Zero the output accumulator (poisoned to 0xAA by the harness).
// ---------------------------------------------------------------------------
__global__ void zero_out_kernel(float* __restrict__ out, int n)
{
    int i = blockIdx.x * blockDim.x + threadIdx.x;
    int n4 = n >> 2;
    float4* out4 = reinterpret_cast<float4*>(out);
    for (int k = i; k < n4; k += gridDim.x * blockDim.x)
        out4[k] = make_float4(0.f, 0.f, 0.f, 0.f);
    int tail_start = n4 << 2;
    for (int k = tail_start + i; k < n; k += gridDim.x * blockDim.x)
        out[k] = 0.f;
}

// ---------------------------------------------------------------------------
// Per-edge kernel factor f(d) = csw*E_shd + sw*E_ord  (qi/KEHALF deferred)
// ---------------------------------------------------------------------------
__device__ __forceinline__ float edge_factor(float d)
{
    float s2    = fmaf(d, d, 1.0f);
    float r     = rsqrtf(s2);          // 1/d_sh
    float dsh   = s2 * r;              // d_sh
    float inv_d = __fdividef(1.0f, d); // 1/d

    float E_ord = fmaf(d,   INV_LR2, inv_d) - TWO_OVER_LC;
    float E_shd = fmaf(dsh, INV_LR2, r)     - TWO_OVER_LC;

    // smooth switch: 6x^5 - 15x^4 + 10x^3 for d < SHORT_CUT, else 1
    float x  = d * INV_SHORT;
    float x3 = x * x * x;
    float sw = fmaf(fmaf(6.0f, x, -15.0f), x, 10.0f) * x3;
    sw = (d < SHORT_CUT) ? sw : 1.0f;

    // csw*E_shd + sw*E_ord == E_shd + sw*(E_ord - E_shd)
    return fmaf(sw, E_ord - E_shd, E_shd);
}

// ---------------------------------------------------------------------------
// Main kernel: accumulate S[i] = sum_e qj * f(d) into out (no qi gather).
// 8 edges per thread, two float4/int4 packets per stream.
// ---------------------------------------------------------------------------
#define EPT 8

__global__ void __launch_bounds__(256)
edges_kernel(const float* __restrict__ charges,
             const float* __restrict__ distances,
             const int*   __restrict__ idx_i,
             const int*   __restrict__ idx_j,
             float*       __restrict__ out,
             int n_edges)
{
    long long t    = blockIdx.x * (long long)blockDim.x + threadIdx.x;
    long long base = t * EPT;

    if (base + EPT <= n_edges) {
        float dv[EPT]; int iv[EPT], jv[EPT];

#pragma unroll
        for (int p = 0; p < EPT / 4; p++) {
            float4 d4 = reinterpret_cast<const float4*>(distances + base)[p];
            int4   i4 = reinterpret_cast<const int4*>(idx_i + base)[p];
            int4   j4 = reinterpret_cast<const int4*>(idx_j + base)[p];
            dv[p*4+0] = d4.x; dv[p*4+1] = d4.y; dv[p*4+2] = d4.z; dv[p*4+3] = d4.w;
            iv[p*4+0] = i4.x; iv[p*4+1] = i4.y; iv[p*4+2] = i4.z; iv[p*4+3] = i4.w;
            jv[p*4+0] = j4.x; jv[p*4+1] = j4.y; jv[p*4+2] = j4.z; jv[p*4+3] = j4.w;
        }

        // single gather stream: qj only, predicated on active
        float qj[EPT];
        bool  act[EPT];
#pragma unroll
        for (int k = 0; k < EPT; k++) {
            act[k] = (dv[k] <= LONG_CUT);
            qj[k]  = act[k] ? __ldg(&charges[jv[k]]) : 0.f;
        }

#pragma unroll
        for (int k = 0; k < EPT; k++) {
            if (act[k]) {
                float e = qj[k] * edge_factor(dv[k]);
                atomicAdd(&out[iv[k]], e);   // result unused -> RED
            }
        }
    } else if (base < n_edges) {
        for (long long e_idx = base; e_idx < n_edges; e_idx++) {
            float d = distances[e_idx];
            if (d <= LONG_CUT) {
                float qj = __ldg(&charges[idx_j[e_idx]]);
                atomicAdd(&out[idx_i[e_idx]], qj * edge_factor(d));
            }
        }
    }
}

// ---------------------------------------------------------------------------
// Epilogue: out[i] = KEHALF * charges[i] * S[i]   (streaming, ~2us)
// ---------------------------------------------------------------------------
__global__ void epilogue_kernel(const float* __restrict__ charges,
                                float* __restrict__ out, int n)
{
    int i = blockIdx.x * blockDim.x + threadIdx.x;
    int n4 = n >> 2;
    const float4* q4 = reinterpret_cast<const float4*>(charges);
    float4*       o4 = reinterpret_cast<float4*>(out);
    for (int k = i; k < n4; k += gridDim.x * blockDim.x) {
        float4 q = q4[k];
        float4 s = o4[k];
        s.x *= KEHALF * q.x;
        s.y *= KEHALF * q.y;
        s.z *= KEHALF * q.z;
        s.w *= KEHALF * q.w;
        o4[k] = s;
    }
    int tail_start = n4 << 2;
    for (int k = tail_start + i; k < n; k += gridDim.x * blockDim.x)
        out[k] *= KEHALF * charges[k];
}

// ---------------------------------------------------------------------------
// Launch
// ---------------------------------------------------------------------------
extern "C" void kernel_launch(void* const* d_in, const int* in_sizes, int n_in,
                              void* d_out, int out_size)
{
    const float* charges   = (const float*)d_in[0];
    const float* distances = (const float*)d_in[1];
    const int*   idx_i     = (const int*)d_in[2];
    const int*   idx_j     = (const int*)d_in[3];
    float*       out       = (float*)d_out;

    int n_edges = in_sizes[1];
    int n_atoms = in_sizes[0];

    // 1) zero accumulator
    {
        int threads = 256;
        int blocks  = (out_size / 4 + threads - 1) / threads;
        if (blocks < 1) blocks = 1;
        if (blocks > 4096) blocks = 4096;
        zero_out_kernel<<<blocks, threads>>>(out, out_size);
    }

    // 2) edge accumulation (no qi gather)
    {
        long long n_thr = ((long long)n_edges + EPT - 1) / EPT;
        int threads = 256;
        long long blocks = (n_thr + threads - 1) / threads;
        edges_kernel<<<(unsigned)blocks, threads>>>(charges, distances,
                                                    idx_i, idx_j, out, n_edges);
    }

    // 3) multiply by KEHALF * qi
    {
        int threads = 256;
        int blocks  = (n_atoms / 4 + threads - 1) / threads;
        if (blocks < 1) blocks = 1;
        if (blocks > 4096) blocks = 4096;
        epilogue_kernel<<<blocks, threads>>>(charges, out, n_atoms);
    }
}